// round 12
// baseline (speedup 1.0000x reference)
#include <cuda_runtime.h>
#include <cuda_bf16.h>
#include <cstdint>
#include <math.h>

// ---------------------------------------------------------------------------
// DeepSeek V2 decoder layer via mma.sync HMMA (bf16 hi/lo split, fp32 acc).
// R11 + single-barrier GEMM main loop + vectorized swiglu.
// ---------------------------------------------------------------------------

#define S_  2048
#define D_  2048
#define H_  16
#define QL_ 1536
#define KVL_ 512
#define DN_ 128
#define DR_ 64
#define DV_ 128
#define I_  8192
#define EPS_ 1e-6f
#define SCALE_ 0.07216878364870323f   // 192^-0.5
#define CF_ 576
#define DF_ 192
#define NQKV_ 2112                    // QL + CF

// ------------------------- fp32 scratch -------------------------------------
#define OFF_QKV      0L
#define OFF_SCORES   (OFF_QKV    + (long)S_*NQKV_)
#define OFF_HID2     (OFF_SCORES + (long)H_*S_*S_)
#define OFF_GU       (OFF_HID2   + (long)S_*D_)
#define SCRATCH_TOTAL (OFF_GU    + (long)S_*2*I_)

__device__ __align__(256) float g_scratch[SCRATCH_TOTAL];

// ------------------- bf16 scratch (hi at OFF, lo at OFF+E) ------------------
#define E_HS    ((long)S_*D_)
#define E_QAS   ((long)S_*QL_)
#define E_QS    ((long)S_*H_*DF_)
#define E_QFS   ((long)H_*S_*CF_)
#define E_KFS   ((long)S_*CF_)
#define E_ATT   ((long)H_*S_*S_)
#define E_OLS   ((long)H_*S_*KVL_)
#define E_OS    ((long)S_*D_)
#define E_X2S   ((long)S_*D_)
#define E_ACTS  ((long)S_*I_)
#define E_WQKV  ((long)D_*NQKV_)
#define E_WQB   ((long)QL_*H_*DF_)
#define E_WKC   ((long)H_*DN_*KVL_)
#define E_WVC   ((long)H_*KVL_*DV_)
#define E_WO    ((long)D_*D_)
#define E_WGU   ((long)D_*2*I_)
#define E_WDN   ((long)I_*D_)

#define B_HS    0L
#define B_QAS   (B_HS   + 2*E_HS)
#define B_QS    (B_QAS  + 2*E_QAS)
#define B_QFS   (B_QS   + 2*E_QS)
#define B_KFS   (B_QFS  + 2*E_QFS)
#define B_ATT   (B_KFS  + 2*E_KFS)
#define B_OLS   (B_ATT  + 2*E_ATT)
#define B_OS    (B_OLS  + 2*E_OLS)
#define B_X2S   (B_OS   + 2*E_OS)
#define B_ACTS  (B_X2S  + 2*E_X2S)
#define B_WQKV  (B_ACTS + 2*E_ACTS)
#define B_WQB   (B_WQKV + 2*E_WQKV)
#define B_WKC   (B_WQB  + 2*E_WQB)
#define B_WVC   (B_WKC  + 2*E_WKC)
#define B_WO    (B_WVC  + 2*E_WVC)
#define B_WGU   (B_WO   + 2*E_WO)
#define B_WDN   (B_WGU  + 2*E_WGU)
#define BF_TOTAL (B_WDN + 2*E_WDN)

__device__ __align__(256) __nv_bfloat16 g_bf[BF_TOTAL];

// ---------------------------------------------------------------------------
// low-level helpers (base-target instructions only, sm_80+)
// ---------------------------------------------------------------------------
__device__ __forceinline__ uint32_t smem_u32(const void* p) {
    uint32_t a;
    asm("{ .reg .u64 t; cvta.to.shared.u64 t, %1; cvt.u32.u64 %0, t; }"
        : "=r"(a) : "l"(p));
    return a;
}
__device__ __forceinline__ void ldmat_x4(uint32_t* r, uint32_t addr) {
    asm volatile("ldmatrix.sync.aligned.m8n8.x4.shared.b16 {%0,%1,%2,%3}, [%4];"
                 : "=r"(r[0]), "=r"(r[1]), "=r"(r[2]), "=r"(r[3]) : "r"(addr));
}
__device__ __forceinline__ void ldmat_x4_t(uint32_t* r, uint32_t addr) {
    asm volatile("ldmatrix.sync.aligned.m8n8.x4.trans.shared.b16 {%0,%1,%2,%3}, [%4];"
                 : "=r"(r[0]), "=r"(r[1]), "=r"(r[2]), "=r"(r[3]) : "r"(addr));
}
__device__ __forceinline__ void mma16816(float* c, const uint32_t* a, const uint32_t* b) {
    asm volatile(
        "mma.sync.aligned.m16n8k16.row.col.f32.bf16.bf16.f32 "
        "{%0,%1,%2,%3}, {%4,%5,%6,%7}, {%8,%9}, {%0,%1,%2,%3};"
        : "+f"(c[0]), "+f"(c[1]), "+f"(c[2]), "+f"(c[3])
        : "r"(a[0]), "r"(a[1]), "r"(a[2]), "r"(a[3]), "r"(b[0]), "r"(b[1]));
}
__device__ __forceinline__ void cp_async16(uint32_t saddr, const void* gptr) {
    asm volatile("cp.async.cg.shared.global [%0], [%1], 16;"
                 :: "r"(saddr), "l"(__cvta_generic_to_global(gptr)));
}
#define CP_COMMIT() asm volatile("cp.async.commit_group;" ::: "memory")
#define CP_WAIT(n)  asm volatile("cp.async.wait_group %0;" :: "n"(n) : "memory")

__device__ __forceinline__ void zfill16(uint32_t saddr) {
    asm volatile("st.shared.v4.b32 [%0], {%1,%1,%1,%1};" :: "r"(saddr), "r"(0) : "memory");
}

// ---------------------------------------------------------------------------
// GEMM: out = alpha * sum_k A[m,k]*B(k,n) (+ add)
// A bf16 hi/lo row-major [M][lda].
// BTRANS=0: B bf16 hi/lo [N][ldb] (K contig). BTRANS=1: B [K][ldb] (N contig).
// 128x128x32 CTA tile, 128 threads (4 warps of 64x64), 2-stage, 2 CTAs/SM.
// Single __syncthreads per K-step (top sync publishes stage t AND retires
// compute(t-1), making buffer (t+1)&1 safe to overwrite).
// causal: 0 none, 1 skip n0 > m0+127, 2 K limited to m0+128.
// ---------------------------------------------------------------------------
#define ROWA   80                          // 32 bf16 = 64B + 16B pad
#define TILE_A (128 * ROWA)                // 10240
#define ROWBT  272                         // 128 bf16 = 256B + 16B pad
#define TILE_BT (32 * ROWBT)               // 8704
#define TILE_BN (128 * ROWA)               // 10240

template <int BTRANS>
__global__ void __launch_bounds__(128, 2)
gemm_tc(const __nv_bfloat16* __restrict__ Ahi, const __nv_bfloat16* __restrict__ Alo,
        int lda, long sA,
        const __nv_bfloat16* __restrict__ Bhi, const __nv_bfloat16* __restrict__ Blo,
        int ldb, long sB,
        float* __restrict__ Cf,
        __nv_bfloat16* __restrict__ Chi, __nv_bfloat16* __restrict__ Clo,
        int ldc, long sC,
        int M, int N, int K, float alpha,
        const float* __restrict__ add, int ldad, long sAd,
        int causal) {
    constexpr int BSZ = BTRANS ? TILE_BT : TILE_BN;
    constexpr int STAGE = 2 * TILE_A + 2 * BSZ;

    const int m0 = blockIdx.x * 128;       // M fast-varying: L2 reuse of B
    const int n0 = blockIdx.y * 128;
    if (causal == 1 && n0 > m0 + 127) return;

    const int bz = blockIdx.z;
    Ahi += (long)bz * sA;  Alo += (long)bz * sA;
    Bhi += (long)bz * sB;  Blo += (long)bz * sB;
    if (Cf)  Cf  += (long)bz * sC;
    if (Chi) { Chi += (long)bz * sC; Clo += (long)bz * sC; }
    if (add) add += (long)bz * sAd;

    const int kmax = (causal == 2) ? min(K, m0 + 128) : K;
    const int nk = kmax / 32;

    extern __shared__ __align__(128) char smem[];
    const uint32_t sbase = smem_u32(smem);
    const int tid = threadIdx.x, lane = tid & 31, wid = tid >> 5;
    const int wm = wid & 1, wn = wid >> 1;  // warp tile: rows wm*64, cols wn*64

    float acc[4][8][4];
    #pragma unroll
    for (int i = 0; i < 4; i++)
        #pragma unroll
        for (int j = 0; j < 8; j++)
            #pragma unroll
            for (int r = 0; r < 4; r++) acc[i][j][r] = 0.f;

    auto load_stage = [&](int t) {
        const int k0 = t * 32;
        const uint32_t sb = sbase + (t & 1) * STAGE;
        #pragma unroll
        for (int i = 0; i < 8; i++) {
            int idx = tid + i * 128;
            int prec = idx >> 9, r = (idx >> 2) & 127, ch = idx & 3;
            uint32_t sa = sb + prec * TILE_A + r * ROWA + ch * 16;
            const __nv_bfloat16* g = prec ? Alo : Ahi;
            cp_async16(sa, g + (long)(m0 + r) * lda + k0 + ch * 8);
        }
        if (BTRANS) {
            #pragma unroll
            for (int i = 0; i < 8; i++) {
                int idx = tid + i * 128;
                int prec = idx >> 9, rem = idx & 511;
                int r = rem >> 4, ch = rem & 15;
                uint32_t sa = sb + 2 * TILE_A + prec * BSZ + r * ROWBT + ch * 16;
                if (n0 + ch * 8 < N) {
                    const __nv_bfloat16* g = prec ? Blo : Bhi;
                    cp_async16(sa, g + (long)(k0 + r) * ldb + n0 + ch * 8);
                } else {
                    zfill16(sa);
                }
            }
        } else {
            #pragma unroll
            for (int i = 0; i < 8; i++) {
                int idx = tid + i * 128;
                int prec = idx >> 9, rem = idx & 511;
                int r = rem >> 2, ch = rem & 3;
                uint32_t sa = sb + 2 * TILE_A + prec * BSZ + r * ROWA + ch * 16;
                if (n0 + r < N) {
                    const __nv_bfloat16* g = prec ? Blo : Bhi;
                    cp_async16(sa, g + (long)(n0 + r) * ldb + k0 + ch * 8);
                } else {
                    zfill16(sa);
                }
            }
        }
        CP_COMMIT();
    };

    auto compute = [&](int st) {
        const uint32_t sb = sbase + st * STAGE;
        #pragma unroll
        for (int kk = 0; kk < 2; kk++) {
            uint32_t ah[4][4], al[4][4];
            uint32_t bh[8][2], bl[8][2];
            #pragma unroll
            for (int mi = 0; mi < 4; mi++) {
                int row = wm * 64 + mi * 16 + (lane & 15);
                uint32_t a = sb + row * ROWA + kk * 32 + ((lane >> 4) & 1) * 16;
                ldmat_x4(ah[mi], a);
                ldmat_x4(al[mi], a + TILE_A);
            }
            if (BTRANS) {
                #pragma unroll
                for (int nb = 0; nb < 4; nb++) {
                    int krow = kk * 16 + (lane & 15);
                    int col = wn * 64 + nb * 16 + ((lane >> 4) & 1) * 8;
                    uint32_t a = sb + 2 * TILE_A + krow * ROWBT + col * 2;
                    uint32_t rh[4], rl[4];
                    ldmat_x4_t(rh, a);
                    ldmat_x4_t(rl, a + BSZ);
                    bh[2 * nb][0] = rh[0]; bh[2 * nb][1] = rh[1];
                    bh[2 * nb + 1][0] = rh[2]; bh[2 * nb + 1][1] = rh[3];
                    bl[2 * nb][0] = rl[0]; bl[2 * nb][1] = rl[1];
                    bl[2 * nb + 1][0] = rl[2]; bl[2 * nb + 1][1] = rl[3];
                }
            } else {
                #pragma unroll
                for (int nb = 0; nb < 4; nb++) {
                    int row = wn * 64 + nb * 16 + ((lane >> 4) & 1) * 8 + (lane & 7);
                    uint32_t a = sb + 2 * TILE_A + row * ROWA + kk * 32 + ((lane >> 3) & 1) * 16;
                    uint32_t rh[4], rl[4];
                    ldmat_x4(rh, a);
                    ldmat_x4(rl, a + BSZ);
                    bh[2 * nb][0] = rh[0]; bh[2 * nb][1] = rh[1];
                    bh[2 * nb + 1][0] = rh[2]; bh[2 * nb + 1][1] = rh[3];
                    bl[2 * nb][0] = rl[0]; bl[2 * nb][1] = rl[1];
                    bl[2 * nb + 1][0] = rl[2]; bl[2 * nb + 1][1] = rl[3];
                }
            }
            #pragma unroll
            for (int mi = 0; mi < 4; mi++)
                #pragma unroll
                for (int ni = 0; ni < 8; ni++) {
                    mma16816(acc[mi][ni], ah[mi], bh[ni]);
                    mma16816(acc[mi][ni], ah[mi], bl[ni]);
                    mma16816(acc[mi][ni], al[mi], bh[ni]);
                }
        }
    };

    // single-barrier 2-stage pipeline
    load_stage(0);
    for (int t = 0; t < nk; t++) {
        CP_WAIT(0);            // load(t) complete (it overlapped compute(t-1))
        __syncthreads();       // publish stage t; retire compute(t-1) reads
        if (t + 1 < nk) load_stage(t + 1);   // overlaps compute(t)
        compute(t & 1);
    }

    // epilogue
    #pragma unroll
    for (int mi = 0; mi < 4; mi++) {
        #pragma unroll
        for (int ni = 0; ni < 8; ni++) {
            long row = m0 + wm * 64 + mi * 16 + (lane >> 2);
            int col = n0 + wn * 64 + ni * 8 + (lane & 3) * 2;
            if (col >= N) continue;
            float vx0 = alpha * acc[mi][ni][0];
            float vy0 = alpha * acc[mi][ni][1];
            float vx1 = alpha * acc[mi][ni][2];
            float vy1 = alpha * acc[mi][ni][3];
            if (add) {
                float2 r0 = *(const float2*)&add[row * ldad + col];
                float2 r1 = *(const float2*)&add[(row + 8) * ldad + col];
                vx0 += r0.x; vy0 += r0.y; vx1 += r1.x; vy1 += r1.y;
            }
            if (Cf) {
                *(float2*)&Cf[row * ldc + col] = make_float2(vx0, vy0);
                *(float2*)&Cf[(row + 8) * ldc + col] = make_float2(vx1, vy1);
            }
            if (Chi) {
                __nv_bfloat16 h0 = __float2bfloat16(vx0), h1 = __float2bfloat16(vy0);
                __nv_bfloat16 h2 = __float2bfloat16(vx1), h3 = __float2bfloat16(vy1);
                *(__nv_bfloat162*)&Chi[row * ldc + col] = __nv_bfloat162(h0, h1);
                *(__nv_bfloat162*)&Chi[(row + 8) * ldc + col] = __nv_bfloat162(h2, h3);
                *(__nv_bfloat162*)&Clo[row * ldc + col] =
                    __nv_bfloat162(__float2bfloat16(vx0 - __bfloat162float(h0)),
                                   __float2bfloat16(vy0 - __bfloat162float(h1)));
                *(__nv_bfloat162*)&Clo[(row + 8) * ldc + col] =
                    __nv_bfloat162(__float2bfloat16(vx1 - __bfloat162float(h2)),
                                   __float2bfloat16(vy1 - __bfloat162float(h3)));
            }
        }
    }
}

// ---------------------------------------------------------------------------
// merged weight split: one kernel handles up to 8 jobs.
// ---------------------------------------------------------------------------
struct SplitJob {
    const float* src;
    __nv_bfloat16 *hi, *lo;
    long n4;
    int C, ldd, col0;
};
struct SplitJobs {
    SplitJob j[8];
    long pre[9];
};

__global__ void split_all_kernel(SplitJobs jobs) {
    long i = (long)blockIdx.x * blockDim.x + threadIdx.x;
    if (i >= jobs.pre[8]) return;
    int k = 0;
    #pragma unroll
    for (int t = 0; t < 8; t++) if (i >= jobs.pre[t + 1]) k = t + 1;
    const SplitJob& J = jobs.j[k];
    long li = i - jobs.pre[k];
    float4 v = ((const float4*)J.src)[li];
    long e = li * 4;
    long r = e / J.C, c = e % J.C;
    long o = r * (long)J.ldd + J.col0 + c;
    __nv_bfloat16 h0 = __float2bfloat16(v.x), h1 = __float2bfloat16(v.y);
    __nv_bfloat16 h2 = __float2bfloat16(v.z), h3 = __float2bfloat16(v.w);
    *(__nv_bfloat162*)&J.hi[o]     = __nv_bfloat162(h0, h1);
    *(__nv_bfloat162*)&J.hi[o + 2] = __nv_bfloat162(h2, h3);
    *(__nv_bfloat162*)&J.lo[o]     = __nv_bfloat162(__float2bfloat16(v.x - __bfloat162float(h0)),
                                                    __float2bfloat16(v.y - __bfloat162float(h1)));
    *(__nv_bfloat162*)&J.lo[o + 2] = __nv_bfloat162(__float2bfloat16(v.z - __bfloat162float(h2)),
                                                    __float2bfloat16(v.w - __bfloat162float(h3)));
}

// ---------------------------------------------------------------------------
// block reductions
// ---------------------------------------------------------------------------
__device__ __forceinline__ float blockReduceSum(float v) {
    __shared__ float red[32];
    int lane = threadIdx.x & 31, w = threadIdx.x >> 5;
    #pragma unroll
    for (int o = 16; o; o >>= 1) v += __shfl_xor_sync(0xffffffffu, v, o);
    if (lane == 0) red[w] = v;
    __syncthreads();
    if (w == 0) {
        float x = (lane < (int)(blockDim.x >> 5)) ? red[lane] : 0.f;
        #pragma unroll
        for (int o = 16; o; o >>= 1) x += __shfl_xor_sync(0xffffffffu, x, o);
        if (lane == 0) red[0] = x;
    }
    __syncthreads();
    float r = red[0];
    __syncthreads();
    return r;
}
__device__ __forceinline__ float blockReduceMax(float v) {
    __shared__ float red[32];
    int lane = threadIdx.x & 31, w = threadIdx.x >> 5;
    #pragma unroll
    for (int o = 16; o; o >>= 1) v = fmaxf(v, __shfl_xor_sync(0xffffffffu, v, o));
    if (lane == 0) red[w] = v;
    __syncthreads();
    if (w == 0) {
        float x = (lane < (int)(blockDim.x >> 5)) ? red[lane] : -3.4e38f;
        #pragma unroll
        for (int o = 16; o; o >>= 1) x = fmaxf(x, __shfl_xor_sync(0xffffffffu, x, o));
        if (lane == 0) red[0] = x;
    }
    __syncthreads();
    float r = red[0];
    __syncthreads();
    return r;
}

// ---------------------------------------------------------------------------
// rmsnorm with strided input and fused hi/lo split output
// ---------------------------------------------------------------------------
__global__ void rmsnorm_split_kernel(const float* __restrict__ x, int ldx,
                                     const float* __restrict__ w,
                                     __nv_bfloat16* __restrict__ hi,
                                     __nv_bfloat16* __restrict__ lo, int N) {
    long row = blockIdx.x;
    const float* xr = x + row * ldx;
    float ss = 0.f;
    for (int i = threadIdx.x; i < N; i += blockDim.x) { float v = xr[i]; ss += v * v; }
    ss = blockReduceSum(ss);
    float inv = rsqrtf(ss / (float)N + EPS_);
    for (int i = threadIdx.x; i < N; i += blockDim.x) {
        float v = xr[i] * inv * w[i];
        __nv_bfloat16 h = __float2bfloat16(v);
        hi[row * N + i] = h;
        lo[row * N + i] = __float2bfloat16(v - __bfloat162float(h));
    }
}

// ---------------------------------------------------------------------------
// fused qas-rmsnorm + kprep (reads qkv). grid 2*S.
// ---------------------------------------------------------------------------
__global__ void qas_kprep_kernel(const float* __restrict__ qkv,
                                 const float* __restrict__ qw,
                                 const float* __restrict__ kw,
                                 const float* __restrict__ cosT,
                                 const float* __restrict__ sinT,
                                 __nv_bfloat16* __restrict__ qash,
                                 __nv_bfloat16* __restrict__ qasl,
                                 __nv_bfloat16* __restrict__ kfh,
                                 __nv_bfloat16* __restrict__ kfl) {
    long b = blockIdx.x;
    if (b < S_) {
        long row = b;
        const float* xr = qkv + row * NQKV_;
        float ss = 0.f;
        for (int i = threadIdx.x; i < QL_; i += blockDim.x) { float v = xr[i]; ss += v * v; }
        ss = blockReduceSum(ss);
        float inv = rsqrtf(ss / (float)QL_ + EPS_);
        for (int i = threadIdx.x; i < QL_; i += blockDim.x) {
            float v = xr[i] * inv * qw[i];
            __nv_bfloat16 h = __float2bfloat16(v);
            qash[row * QL_ + i] = h;
            qasl[row * QL_ + i] = __float2bfloat16(v - __bfloat162float(h));
        }
    } else {
        long s = b - S_;
        const float* row = qkv + s * NQKV_ + QL_;
        float ss = 0.f;
        for (int i = threadIdx.x; i < KVL_; i += blockDim.x) { float v = row[i]; ss += v * v; }
        ss = blockReduceSum(ss);
        float inv = rsqrtf(ss / (float)KVL_ + EPS_);
        for (int i = threadIdx.x; i < KVL_; i += blockDim.x) {
            float v = row[i] * inv * kw[i];
            __nv_bfloat16 h = __float2bfloat16(v);
            kfh[s * CF_ + i] = h;
            kfl[s * CF_ + i] = __float2bfloat16(v - __bfloat162float(h));
        }
        int i = threadIdx.x;
        if (i < DR_) {
            float x = row[KVL_ + i];
            float rot = (i < DR_ / 2) ? -row[KVL_ + i + DR_ / 2] : row[KVL_ + i - DR_ / 2];
            float v = x * cosT[s * DR_ + i] + rot * sinT[s * DR_ + i];
            __nv_bfloat16 h = __float2bfloat16(v);
            kfh[s * CF_ + KVL_ + i] = h;
            kfl[s * CF_ + KVL_ + i] = __float2bfloat16(v - __bfloat162float(h));
        }
    }
}

// ---------------------------------------------------------------------------
// q_pe rope. grid (S, H), 64 thr
// ---------------------------------------------------------------------------
__global__ void qrope_kernel(const __nv_bfloat16* __restrict__ qh,
                             const __nv_bfloat16* __restrict__ ql,
                             const float* __restrict__ cosT,
                             const float* __restrict__ sinT,
                             __nv_bfloat16* __restrict__ qfh,
                             __nv_bfloat16* __restrict__ qfl) {
    long s = blockIdx.x;
    int h = blockIdx.y;
    int i = threadIdx.x;
    long base = s * (long)(H_ * DF_) + h * DF_ + DN_;
    float x = __bfloat162float(qh[base + i]) + __bfloat162float(ql[base + i]);
    int j = (i < DR_ / 2) ? (i + DR_ / 2) : (i - DR_ / 2);
    float xr = __bfloat162float(qh[base + j]) + __bfloat162float(ql[base + j]);
    float rot = (i < DR_ / 2) ? -xr : xr;
    float v = x * cosT[s * DR_ + i] + rot * sinT[s * DR_ + i];
    long o = ((long)h * S_ + s) * CF_ + KVL_ + i;
    __nv_bfloat16 hh = __float2bfloat16(v);
    qfh[o] = hh;
    qfl[o] = __float2bfloat16(v - __bfloat162float(hh));
}

// ---------------------------------------------------------------------------
// causal softmax: scores fp32 -> attn hi/lo bf16; zero-fill to tile boundary.
// ---------------------------------------------------------------------------
__global__ void softmax_causal_kernel(const float* __restrict__ scores,
                                      __nv_bfloat16* __restrict__ ah,
                                      __nv_bfloat16* __restrict__ al) {
    long s = blockIdx.x;
    int h = blockIdx.y;
    const float* row = scores + ((long)h * S_ + s) * S_;
    __nv_bfloat16* hrow = ah + ((long)h * S_ + s) * S_;
    __nv_bfloat16* lrow = al + ((long)h * S_ + s) * S_;
    int L = (int)s + 1;
    int Lpad = (((int)s >> 7) + 1) << 7;
    float v[8];
    int cnt = 0;
    float m = -3.4e38f;
    for (int i = threadIdx.x; i < L; i += 256) { v[cnt] = row[i]; m = fmaxf(m, v[cnt]); cnt++; }
    m = blockReduceMax(m);
    float sum = 0.f;
    for (int j = 0; j < cnt; j++) { v[j] = __expf(v[j] - m); sum += v[j]; }
    sum = blockReduceSum(sum);
    float inv = 1.f / sum;
    cnt = 0;
    for (int i = threadIdx.x; i < L; i += 256) {
        float p = v[cnt++] * inv;
        __nv_bfloat16 hh = __float2bfloat16(p);
        hrow[i] = hh;
        lrow[i] = __float2bfloat16(p - __bfloat162float(hh));
    }
    __nv_bfloat16 z = __float2bfloat16(0.f);
    for (int i = L + threadIdx.x; i < Lpad; i += 256) { hrow[i] = z; lrow[i] = z; }
}

// ---------------------------------------------------------------------------
// swiglu: gu fp32 -> act hi/lo (float4 vectorized)
// ---------------------------------------------------------------------------
__global__ void swiglu_kernel(const float* __restrict__ gu,
                              __nv_bfloat16* __restrict__ ah,
                              __nv_bfloat16* __restrict__ al) {
    long i4 = (long)blockIdx.x * blockDim.x + threadIdx.x;
    if (i4 >= (long)S_ * I_ / 4) return;
    long s = i4 / (I_ / 4), c4 = i4 % (I_ / 4);
    float4 g = *(const float4*)&gu[s * (2L * I_) + c4 * 4];
    float4 u = *(const float4*)&gu[s * (2L * I_) + I_ + c4 * 4];
    float v0 = (g.x / (1.f + __expf(-g.x))) * u.x;
    float v1 = (g.y / (1.f + __expf(-g.y))) * u.y;
    float v2 = (g.z / (1.f + __expf(-g.z))) * u.z;
    float v3 = (g.w / (1.f + __expf(-g.w))) * u.w;
    __nv_bfloat16 h0 = __float2bfloat16(v0), h1 = __float2bfloat16(v1);
    __nv_bfloat16 h2 = __float2bfloat16(v2), h3 = __float2bfloat16(v3);
    long o = s * (long)I_ + c4 * 4;
    *(__nv_bfloat162*)&ah[o]     = __nv_bfloat162(h0, h1);
    *(__nv_bfloat162*)&ah[o + 2] = __nv_bfloat162(h2, h3);
    *(__nv_bfloat162*)&al[o]     = __nv_bfloat162(__float2bfloat16(v0 - __bfloat162float(h0)),
                                                  __float2bfloat16(v1 - __bfloat162float(h1)));
    *(__nv_bfloat162*)&al[o + 2] = __nv_bfloat162(__float2bfloat16(v2 - __bfloat162float(h2)),
                                                  __float2bfloat16(v3 - __bfloat162float(h3)));
}

// ---------------------------------------------------------------------------
// host orchestration
// ---------------------------------------------------------------------------
#define SMEM_T  (2 * (2 * TILE_A + 2 * TILE_BT))   // 75776
#define SMEM_NT (2 * (2 * TILE_A + 2 * TILE_BN))   // 81920

struct GArgs {
    const __nv_bfloat16 *Ah, *Al, *Bh, *Bl;
    int lda, ldb, ldc, M, N, K, batch, causal, ldad;
    long sA, sB, sC, sAd;
    float *Cf, alpha;
    __nv_bfloat16 *Chi, *Clo;
    const float* add;
};

static void launch_g(bool btrans, const GArgs& a, cudaStream_t st) {
    dim3 grid(a.M / 128, (a.N + 127) / 128, a.batch);
    if (btrans)
        gemm_tc<1><<<grid, 128, SMEM_T, st>>>(a.Ah, a.Al, a.lda, a.sA, a.Bh, a.Bl, a.ldb, a.sB,
                                              a.Cf, a.Chi, a.Clo, a.ldc, a.sC,
                                              a.M, a.N, a.K, a.alpha, a.add, a.ldad, a.sAd, a.causal);
    else
        gemm_tc<0><<<grid, 128, SMEM_NT, st>>>(a.Ah, a.Al, a.lda, a.sA, a.Bh, a.Bl, a.ldb, a.sB,
                                               a.Cf, a.Chi, a.Clo, a.ldc, a.sC,
                                               a.M, a.N, a.K, a.alpha, a.add, a.ldad, a.sAd, a.causal);
}

extern "C" void kernel_launch(void* const* d_in, const int* in_sizes, int n_in,
                              void* d_out, int out_size) {
    const float* hidden    = (const float*)d_in[0];
    const float* cosT      = (const float*)d_in[1];
    const float* sinT      = (const float*)d_in[2];
    const float* ln1_w     = (const float*)d_in[3];
    const float* q_a_w     = (const float*)d_in[4];
    const float* q_a_ln_w  = (const float*)d_in[5];
    const float* q_b_w     = (const float*)d_in[6];
    const float* kv_a_w    = (const float*)d_in[7];
    const float* kv_a_ln_w = (const float*)d_in[8];
    const float* kc_w      = (const float*)d_in[9];
    const float* vc_w      = (const float*)d_in[10];
    const float* o_w       = (const float*)d_in[11];
    const float* ln2_w     = (const float*)d_in[12];
    const float* gate_up_w = (const float*)d_in[13];
    const float* down_w    = (const float*)d_in[14];
    float* out             = (float*)d_out;

    cudaFuncSetAttribute(gemm_tc<1>, cudaFuncAttributeMaxDynamicSharedMemorySize, SMEM_T);
    cudaFuncSetAttribute(gemm_tc<0>, cudaFuncAttributeMaxDynamicSharedMemorySize, SMEM_NT);

    float* sc = nullptr;
    cudaGetSymbolAddress((void**)&sc, g_scratch);
    __nv_bfloat16* bf = nullptr;
    cudaGetSymbolAddress((void**)&bf, g_bf);

    float* qkv    = sc + OFF_QKV;
    float* scores = sc + OFF_SCORES;
    float* hid2   = sc + OFF_HID2;
    float* gu     = sc + OFF_GU;

    auto HI = [&](long off) { return bf + off; };
    auto LO = [&](long off, long E) { return bf + off + E; };

    // side stream + events
    cudaStream_t s2;
    cudaStreamCreate(&s2);
    cudaEvent_t e0, e_w, e_att, e_s0;
    cudaEventCreateWithFlags(&e0,    cudaEventDisableTiming);
    cudaEventCreateWithFlags(&e_w,   cudaEventDisableTiming);
    cudaEventCreateWithFlags(&e_att, cudaEventDisableTiming);
    cudaEventCreateWithFlags(&e_s0,  cudaEventDisableTiming);

    // --- critical weight split (WQKV only) on main ---
    {
        SplitJobs js{};
        js.j[0] = {q_a_w,  HI(B_WQKV), LO(B_WQKV, E_WQKV), ((long)D_ * QL_) / 4, QL_, NQKV_, 0};
        js.j[1] = {kv_a_w, HI(B_WQKV), LO(B_WQKV, E_WQKV), ((long)D_ * CF_) / 4, CF_, NQKV_, QL_};
        js.pre[0] = 0;
        for (int k = 0; k < 8; k++) js.pre[k + 1] = js.pre[k] + js.j[k].n4;
        split_all_kernel<<<(unsigned)((js.pre[8] + 255) / 256), 256>>>(js);
    }

    // fork: remaining weight splits on s2
    cudaEventRecord(e0, 0);
    cudaStreamWaitEvent(s2, e0, 0);
    {
        SplitJobs js{};
        js.j[0] = {q_b_w,     HI(B_WQB), LO(B_WQB, E_WQB), E_WQB / 4, H_ * DF_, H_ * DF_, 0};
        js.j[1] = {kc_w,      HI(B_WKC), LO(B_WKC, E_WKC), E_WKC / 4, KVL_, KVL_, 0};
        js.j[2] = {vc_w,      HI(B_WVC), LO(B_WVC, E_WVC), E_WVC / 4, DV_, DV_, 0};
        js.j[3] = {o_w,       HI(B_WO),  LO(B_WO,  E_WO),  E_WO / 4,  D_, D_, 0};
        js.j[4] = {gate_up_w, HI(B_WGU), LO(B_WGU, E_WGU), E_WGU / 4, 2 * I_, 2 * I_, 0};
        js.j[5] = {down_w,    HI(B_WDN), LO(B_WDN, E_WDN), E_WDN / 4, D_, D_, 0};
        js.pre[0] = 0;
        for (int k = 0; k < 8; k++) js.pre[k + 1] = js.pre[k] + js.j[k].n4;
        split_all_kernel<<<(unsigned)((js.pre[8] + 255) / 256), 256, 0, s2>>>(js);
    }
    cudaEventRecord(e_w, s2);

    // 1. h = rmsnorm(hidden) -> hi/lo
    rmsnorm_split_kernel<<<S_, 256>>>(hidden, D_, ln1_w, HI(B_HS), LO(B_HS, E_HS), D_);

    GArgs a{};

    // 2. qkv = h @ [q_a_w | kv_a_w]   (fused, fp32 out, N=2112)
    a = {HI(B_HS), LO(B_HS, E_HS), HI(B_WQKV), LO(B_WQKV, E_WQKV),
         D_, NQKV_, NQKV_, S_, NQKV_, D_, 1, 0, 0, 0, 0, 0, 0,
         qkv, 1.f, nullptr, nullptr, nullptr};
    launch_g(true, a, 0);

    // 3+5. fused: qas = rmsnorm(qkv[:, :1536]); kf = [rmsnorm, rope] -> hi/lo
    qas_kprep_kernel<<<2 * S_, 256>>>(qkv, q_a_ln_w, kv_a_ln_w, cosT, sinT,
                                      HI(B_QAS), LO(B_QAS, E_QAS),
                                      HI(B_KFS), LO(B_KFS, E_KFS));

    // join: all weights split before the q GEMM
    cudaStreamWaitEvent(0, e_w, 0);

    // 4. q = qas @ q_b_w -> hi/lo
    a = {HI(B_QAS), LO(B_QAS, E_QAS), HI(B_WQB), LO(B_WQB, E_WQB),
         QL_, H_ * DF_, H_ * DF_, S_, H_ * DF_, QL_, 1, 0, 0, 0, 0, 0, 0,
         nullptr, 1.f, HI(B_QS), LO(B_QS, E_QS), nullptr};
    launch_g(true, a, 0);

    // 6. qf[:, :512] = q_nope @ kc_w per head -> hi/lo
    a = {HI(B_QS), LO(B_QS, E_QS), HI(B_WKC), LO(B_WKC, E_WKC),
         H_ * DF_, KVL_, CF_, S_, KVL_, DN_, H_, 0, 0,
         (long)DF_, (long)DN_ * KVL_, (long)S_ * CF_, 0,
         nullptr, 1.f, HI(B_QFS), LO(B_QFS, E_QFS), nullptr};
    launch_g(true, a, 0);

    // 7. qf[:, 512:576] = rope(q_pe) -> hi/lo
    qrope_kernel<<<dim3(S_, H_), DR_>>>(HI(B_QS), LO(B_QS, E_QS), cosT, sinT,
                                        HI(B_QFS), LO(B_QFS, E_QFS));

    // ---- attention pipelined in two head-groups (8 heads each) ----
    const int HG = H_ / 2;

    // 8a. scores group0 on main
    a = {HI(B_QFS), LO(B_QFS, E_QFS), HI(B_KFS), LO(B_KFS, E_KFS),
         CF_, CF_, S_, S_, S_, CF_, HG, 1, 0,
         (long)S_ * CF_, 0, (long)S_ * S_, 0,
         scores, SCALE_, nullptr, nullptr, nullptr};
    launch_g(false, a, 0);
    cudaEventRecord(e_s0, 0);

    // 8b. scores group1 on main
    a.Ah = HI(B_QFS) + (long)HG * S_ * CF_;
    a.Al = LO(B_QFS, E_QFS) + (long)HG * S_ * CF_;
    a.Cf = scores + (long)HG * S_ * S_;
    launch_g(false, a, 0);

    // 9a+10a. softmax+olat group0 on s2 (overlaps scores group1)
    cudaStreamWaitEvent(s2, e_s0, 0);
    softmax_causal_kernel<<<dim3(S_, HG), 256, 0, s2>>>(
        scores, HI(B_ATT), LO(B_ATT, E_ATT));
    a = {HI(B_ATT), LO(B_ATT, E_ATT), HI(B_KFS), LO(B_KFS, E_KFS),
         S_, CF_, KVL_, S_, KVL_, S_, HG, 2, 0,
         (long)S_ * S_, 0, (long)S_ * KVL_, 0,
         nullptr, 1.f, HI(B_OLS), LO(B_OLS, E_OLS), nullptr};
    launch_g(true, a, s2);
    cudaEventRecord(e_att, s2);

    // 9b+10b. softmax+olat group1 on main
    softmax_causal_kernel<<<dim3(S_, HG), 256>>>(
        scores + (long)HG * S_ * S_,
        HI(B_ATT) + (long)HG * S_ * S_,
        LO(B_ATT, E_ATT) + (long)HG * S_ * S_);
    a = {HI(B_ATT) + (long)HG * S_ * S_, LO(B_ATT, E_ATT) + (long)HG * S_ * S_,
         HI(B_KFS), LO(B_KFS, E_KFS),
         S_, CF_, KVL_, S_, KVL_, S_, HG, 2, 0,
         (long)S_ * S_, 0, (long)S_ * KVL_, 0,
         nullptr, 1.f, HI(B_OLS) + (long)HG * S_ * KVL_,
         LO(B_OLS, E_OLS) + (long)HG * S_ * KVL_, nullptr};
    launch_g(true, a, 0);

    // join: all olat done before vc GEMM
    cudaStreamWaitEvent(0, e_att, 0);

    // 11. o[:, h*128:] = olat @ vc_w per head -> hi/lo
    a = {HI(B_OLS), LO(B_OLS, E_OLS), HI(B_WVC), LO(B_WVC, E_WVC),
         KVL_, DV_, H_ * DV_, S_, DV_, KVL_, H_, 0, 0,
         (long)S_ * KVL_, (long)KVL_ * DV_, (long)DV_, 0,
         nullptr, 1.f, HI(B_OS), LO(B_OS, E_OS), nullptr};
    launch_g(true, a, 0);

    // 12. hid2 = o @ o_w + hidden  (fp32)
    a = {HI(B_OS), LO(B_OS, E_OS), HI(B_WO), LO(B_WO, E_WO),
         H_ * DV_, D_, D_, S_, D_, H_ * DV_, 1, 0, D_, 0, 0, 0, 0,
         hid2, 1.f, nullptr, nullptr, hidden};
    launch_g(true, a, 0);

    // 13. x2 = rmsnorm(hid2) -> hi/lo
    rmsnorm_split_kernel<<<S_, 256>>>(hid2, D_, ln2_w, HI(B_X2S), LO(B_X2S, E_X2S), D_);

    // 14. gu = x2 @ gate_up_w  (fp32)
    a = {HI(B_X2S), LO(B_X2S, E_X2S), HI(B_WGU), LO(B_WGU, E_WGU),
         D_, 2 * I_, 2 * I_, S_, 2 * I_, D_, 1, 0, 0, 0, 0, 0, 0,
         gu, 1.f, nullptr, nullptr, nullptr};
    launch_g(true, a, 0);

    // 15. act = swiglu(gu) -> hi/lo  (float4)
    {
        long total4 = (long)S_ * I_ / 4;
        swiglu_kernel<<<(unsigned)((total4 + 255) / 256), 256>>>(gu, HI(B_ACTS), LO(B_ACTS, E_ACTS));
    }

    // 16. out = act @ down_w + hid2  (fp32)
    a = {HI(B_ACTS), LO(B_ACTS, E_ACTS), HI(B_WDN), LO(B_WDN, E_WDN),
         I_, D_, D_, S_, D_, I_, 1, 0, D_, 0, 0, 0, 0,
         out, 1.f, nullptr, nullptr, hid2};
    launch_g(true, a, 0);
}

// round 14
// speedup vs baseline: 1.0217x; 1.0217x over previous
#include <cuda_runtime.h>
#include <cuda_bf16.h>
#include <cstdint>
#include <math.h>

// ---------------------------------------------------------------------------
// DeepSeek V2 decoder layer via mma.sync HMMA (bf16 hi/lo split, fp32 acc).
// Best-known GEMM loop (R11) + float4 swiglu + dual-stream schedule.
// ---------------------------------------------------------------------------

#define S_  2048
#define D_  2048
#define H_  16
#define QL_ 1536
#define KVL_ 512
#define DN_ 128
#define DR_ 64
#define DV_ 128
#define I_  8192
#define EPS_ 1e-6f
#define SCALE_ 0.07216878364870323f   // 192^-0.5
#define CF_ 576
#define DF_ 192
#define NQKV_ 2112                    // QL + CF

// ------------------------- fp32 scratch -------------------------------------
#define OFF_QKV      0L
#define OFF_SCORES   (OFF_QKV    + (long)S_*NQKV_)
#define OFF_HID2     (OFF_SCORES + (long)H_*S_*S_)
#define OFF_GU       (OFF_HID2   + (long)S_*D_)
#define SCRATCH_TOTAL (OFF_GU    + (long)S_*2*I_)

__device__ __align__(256) float g_scratch[SCRATCH_TOTAL];

// ------------------- bf16 scratch (hi at OFF, lo at OFF+E) ------------------
#define E_HS    ((long)S_*D_)
#define E_QAS   ((long)S_*QL_)
#define E_QS    ((long)S_*H_*DF_)
#define E_QFS   ((long)H_*S_*CF_)
#define E_KFS   ((long)S_*CF_)
#define E_ATT   ((long)H_*S_*S_)
#define E_OLS   ((long)H_*S_*KVL_)
#define E_OS    ((long)S_*D_)
#define E_X2S   ((long)S_*D_)
#define E_ACTS  ((long)S_*I_)
#define E_WQKV  ((long)D_*NQKV_)
#define E_WQB   ((long)QL_*H_*DF_)
#define E_WKC   ((long)H_*DN_*KVL_)
#define E_WVC   ((long)H_*KVL_*DV_)
#define E_WO    ((long)D_*D_)
#define E_WGU   ((long)D_*2*I_)
#define E_WDN   ((long)I_*D_)

#define B_HS    0L
#define B_QAS   (B_HS   + 2*E_HS)
#define B_QS    (B_QAS  + 2*E_QAS)
#define B_QFS   (B_QS   + 2*E_QS)
#define B_KFS   (B_QFS  + 2*E_QFS)
#define B_ATT   (B_KFS  + 2*E_KFS)
#define B_OLS   (B_ATT  + 2*E_ATT)
#define B_OS    (B_OLS  + 2*E_OLS)
#define B_X2S   (B_OS   + 2*E_OS)
#define B_ACTS  (B_X2S  + 2*E_X2S)
#define B_WQKV  (B_ACTS + 2*E_ACTS)
#define B_WQB   (B_WQKV + 2*E_WQKV)
#define B_WKC   (B_WQB  + 2*E_WQB)
#define B_WVC   (B_WKC  + 2*E_WKC)
#define B_WO    (B_WVC  + 2*E_WVC)
#define B_WGU   (B_WO   + 2*E_WO)
#define B_WDN   (B_WGU  + 2*E_WGU)
#define BF_TOTAL (B_WDN + 2*E_WDN)

__device__ __align__(256) __nv_bfloat16 g_bf[BF_TOTAL];

// ---------------------------------------------------------------------------
// low-level helpers (base-target instructions only, sm_80+)
// ---------------------------------------------------------------------------
__device__ __forceinline__ uint32_t smem_u32(const void* p) {
    uint32_t a;
    asm("{ .reg .u64 t; cvta.to.shared.u64 t, %1; cvt.u32.u64 %0, t; }"
        : "=r"(a) : "l"(p));
    return a;
}
__device__ __forceinline__ void ldmat_x4(uint32_t* r, uint32_t addr) {
    asm volatile("ldmatrix.sync.aligned.m8n8.x4.shared.b16 {%0,%1,%2,%3}, [%4];"
                 : "=r"(r[0]), "=r"(r[1]), "=r"(r[2]), "=r"(r[3]) : "r"(addr));
}
__device__ __forceinline__ void ldmat_x4_t(uint32_t* r, uint32_t addr) {
    asm volatile("ldmatrix.sync.aligned.m8n8.x4.trans.shared.b16 {%0,%1,%2,%3}, [%4];"
                 : "=r"(r[0]), "=r"(r[1]), "=r"(r[2]), "=r"(r[3]) : "r"(addr));
}
__device__ __forceinline__ void mma16816(float* c, const uint32_t* a, const uint32_t* b) {
    asm volatile(
        "mma.sync.aligned.m16n8k16.row.col.f32.bf16.bf16.f32 "
        "{%0,%1,%2,%3}, {%4,%5,%6,%7}, {%8,%9}, {%0,%1,%2,%3};"
        : "+f"(c[0]), "+f"(c[1]), "+f"(c[2]), "+f"(c[3])
        : "r"(a[0]), "r"(a[1]), "r"(a[2]), "r"(a[3]), "r"(b[0]), "r"(b[1]));
}
__device__ __forceinline__ void cp_async16(uint32_t saddr, const void* gptr) {
    asm volatile("cp.async.cg.shared.global [%0], [%1], 16;"
                 :: "r"(saddr), "l"(__cvta_generic_to_global(gptr)));
}
#define CP_COMMIT() asm volatile("cp.async.commit_group;" ::: "memory")
#define CP_WAIT(n)  asm volatile("cp.async.wait_group %0;" :: "n"(n) : "memory")

__device__ __forceinline__ void zfill16(uint32_t saddr) {
    asm volatile("st.shared.v4.b32 [%0], {%1,%1,%1,%1};" :: "r"(saddr), "r"(0) : "memory");
}

// ---------------------------------------------------------------------------
// GEMM: out = alpha * sum_k A[m,k]*B(k,n) (+ add)
// A bf16 hi/lo row-major [M][lda].
// BTRANS=0: B bf16 hi/lo [N][ldb] (K contig). BTRANS=1: B [K][ldb] (N contig).
// 128x128x32 CTA tile, 128 threads (4 warps of 64x64), 2-stage, 2 CTAs/SM.
// causal: 0 none, 1 skip n0 > m0+127, 2 K limited to m0+128.
// ---------------------------------------------------------------------------
#define ROWA   80                          // 32 bf16 = 64B + 16B pad
#define TILE_A (128 * ROWA)                // 10240
#define ROWBT  272                         // 128 bf16 = 256B + 16B pad
#define TILE_BT (32 * ROWBT)               // 8704
#define TILE_BN (128 * ROWA)               // 10240

template <int BTRANS>
__global__ void __launch_bounds__(128, 2)
gemm_tc(const __nv_bfloat16* __restrict__ Ahi, const __nv_bfloat16* __restrict__ Alo,
        int lda, long sA,
        const __nv_bfloat16* __restrict__ Bhi, const __nv_bfloat16* __restrict__ Blo,
        int ldb, long sB,
        float* __restrict__ Cf,
        __nv_bfloat16* __restrict__ Chi, __nv_bfloat16* __restrict__ Clo,
        int ldc, long sC,
        int M, int N, int K, float alpha,
        const float* __restrict__ add, int ldad, long sAd,
        int causal) {
    constexpr int BSZ = BTRANS ? TILE_BT : TILE_BN;
    constexpr int STAGE = 2 * TILE_A + 2 * BSZ;

    const int m0 = blockIdx.x * 128;       // M fast-varying: L2 reuse of B
    const int n0 = blockIdx.y * 128;
    if (causal == 1 && n0 > m0 + 127) return;

    const int bz = blockIdx.z;
    Ahi += (long)bz * sA;  Alo += (long)bz * sA;
    Bhi += (long)bz * sB;  Blo += (long)bz * sB;
    if (Cf)  Cf  += (long)bz * sC;
    if (Chi) { Chi += (long)bz * sC; Clo += (long)bz * sC; }
    if (add) add += (long)bz * sAd;

    const int kmax = (causal == 2) ? min(K, m0 + 128) : K;
    const int nk = kmax / 32;

    extern __shared__ __align__(128) char smem[];
    const uint32_t sbase = smem_u32(smem);
    const int tid = threadIdx.x, lane = tid & 31, wid = tid >> 5;
    const int wm = wid & 1, wn = wid >> 1;  // warp tile: rows wm*64, cols wn*64

    float acc[4][8][4];
    #pragma unroll
    for (int i = 0; i < 4; i++)
        #pragma unroll
        for (int j = 0; j < 8; j++)
            #pragma unroll
            for (int r = 0; r < 4; r++) acc[i][j][r] = 0.f;

    auto load_stage = [&](int t) {
        const int k0 = t * 32;
        const uint32_t sb = sbase + (t & 1) * STAGE;
        #pragma unroll
        for (int i = 0; i < 8; i++) {
            int idx = tid + i * 128;
            int prec = idx >> 9, r = (idx >> 2) & 127, ch = idx & 3;
            uint32_t sa = sb + prec * TILE_A + r * ROWA + ch * 16;
            const __nv_bfloat16* g = prec ? Alo : Ahi;
            cp_async16(sa, g + (long)(m0 + r) * lda + k0 + ch * 8);
        }
        if (BTRANS) {
            #pragma unroll
            for (int i = 0; i < 8; i++) {
                int idx = tid + i * 128;
                int prec = idx >> 9, rem = idx & 511;
                int r = rem >> 4, ch = rem & 15;
                uint32_t sa = sb + 2 * TILE_A + prec * BSZ + r * ROWBT + ch * 16;
                if (n0 + ch * 8 < N) {
                    const __nv_bfloat16* g = prec ? Blo : Bhi;
                    cp_async16(sa, g + (long)(k0 + r) * ldb + n0 + ch * 8);
                } else {
                    zfill16(sa);
                }
            }
        } else {
            #pragma unroll
            for (int i = 0; i < 8; i++) {
                int idx = tid + i * 128;
                int prec = idx >> 9, rem = idx & 511;
                int r = rem >> 2, ch = rem & 3;
                uint32_t sa = sb + 2 * TILE_A + prec * BSZ + r * ROWA + ch * 16;
                if (n0 + r < N) {
                    const __nv_bfloat16* g = prec ? Blo : Bhi;
                    cp_async16(sa, g + (long)(n0 + r) * ldb + k0 + ch * 8);
                } else {
                    zfill16(sa);
                }
            }
        }
        CP_COMMIT();
    };

    auto compute = [&](int st) {
        const uint32_t sb = sbase + st * STAGE;
        #pragma unroll
        for (int kk = 0; kk < 2; kk++) {
            uint32_t ah[4][4], al[4][4];
            uint32_t bh[8][2], bl[8][2];
            #pragma unroll
            for (int mi = 0; mi < 4; mi++) {
                int row = wm * 64 + mi * 16 + (lane & 15);
                uint32_t a = sb + row * ROWA + kk * 32 + ((lane >> 4) & 1) * 16;
                ldmat_x4(ah[mi], a);
                ldmat_x4(al[mi], a + TILE_A);
            }
            if (BTRANS) {
                #pragma unroll
                for (int nb = 0; nb < 4; nb++) {
                    int krow = kk * 16 + (lane & 15);
                    int col = wn * 64 + nb * 16 + ((lane >> 4) & 1) * 8;
                    uint32_t a = sb + 2 * TILE_A + krow * ROWBT + col * 2;
                    uint32_t rh[4], rl[4];
                    ldmat_x4_t(rh, a);
                    ldmat_x4_t(rl, a + BSZ);
                    bh[2 * nb][0] = rh[0]; bh[2 * nb][1] = rh[1];
                    bh[2 * nb + 1][0] = rh[2]; bh[2 * nb + 1][1] = rh[3];
                    bl[2 * nb][0] = rl[0]; bl[2 * nb][1] = rl[1];
                    bl[2 * nb + 1][0] = rl[2]; bl[2 * nb + 1][1] = rl[3];
                }
            } else {
                #pragma unroll
                for (int nb = 0; nb < 4; nb++) {
                    int row = wn * 64 + nb * 16 + ((lane >> 4) & 1) * 8 + (lane & 7);
                    uint32_t a = sb + 2 * TILE_A + row * ROWA + kk * 32 + ((lane >> 3) & 1) * 16;
                    uint32_t rh[4], rl[4];
                    ldmat_x4(rh, a);
                    ldmat_x4(rl, a + BSZ);
                    bh[2 * nb][0] = rh[0]; bh[2 * nb][1] = rh[1];
                    bh[2 * nb + 1][0] = rh[2]; bh[2 * nb + 1][1] = rh[3];
                    bl[2 * nb][0] = rl[0]; bl[2 * nb][1] = rl[1];
                    bl[2 * nb + 1][0] = rl[2]; bl[2 * nb + 1][1] = rl[3];
                }
            }
            #pragma unroll
            for (int mi = 0; mi < 4; mi++)
                #pragma unroll
                for (int ni = 0; ni < 8; ni++) {
                    mma16816(acc[mi][ni], ah[mi], bh[ni]);
                    mma16816(acc[mi][ni], ah[mi], bl[ni]);
                    mma16816(acc[mi][ni], al[mi], bh[ni]);
                }
        }
    };

    // proven 2-stage pipeline: issue load(t+1) BEFORE waiting on load(t)
    load_stage(0);
    for (int t = 0; t < nk; t++) {
        if (t + 1 < nk) { load_stage(t + 1); CP_WAIT(1); }
        else            { CP_WAIT(0); }
        __syncthreads();
        compute(t & 1);
        __syncthreads();
    }

    // epilogue
    #pragma unroll
    for (int mi = 0; mi < 4; mi++) {
        #pragma unroll
        for (int ni = 0; ni < 8; ni++) {
            long row = m0 + wm * 64 + mi * 16 + (lane >> 2);
            int col = n0 + wn * 64 + ni * 8 + (lane & 3) * 2;
            if (col >= N) continue;
            float vx0 = alpha * acc[mi][ni][0];
            float vy0 = alpha * acc[mi][ni][1];
            float vx1 = alpha * acc[mi][ni][2];
            float vy1 = alpha * acc[mi][ni][3];
            if (add) {
                float2 r0 = *(const float2*)&add[row * ldad + col];
                float2 r1 = *(const float2*)&add[(row + 8) * ldad + col];
                vx0 += r0.x; vy0 += r0.y; vx1 += r1.x; vy1 += r1.y;
            }
            if (Cf) {
                *(float2*)&Cf[row * ldc + col] = make_float2(vx0, vy0);
                *(float2*)&Cf[(row + 8) * ldc + col] = make_float2(vx1, vy1);
            }
            if (Chi) {
                __nv_bfloat16 h0 = __float2bfloat16(vx0), h1 = __float2bfloat16(vy0);
                __nv_bfloat16 h2 = __float2bfloat16(vx1), h3 = __float2bfloat16(vy1);
                *(__nv_bfloat162*)&Chi[row * ldc + col] = __nv_bfloat162(h0, h1);
                *(__nv_bfloat162*)&Chi[(row + 8) * ldc + col] = __nv_bfloat162(h2, h3);
                *(__nv_bfloat162*)&Clo[row * ldc + col] =
                    __nv_bfloat162(__float2bfloat16(vx0 - __bfloat162float(h0)),
                                   __float2bfloat16(vy0 - __bfloat162float(h1)));
                *(__nv_bfloat162*)&Clo[(row + 8) * ldc + col] =
                    __nv_bfloat162(__float2bfloat16(vx1 - __bfloat162float(h2)),
                                   __float2bfloat16(vy1 - __bfloat162float(h3)));
            }
        }
    }
}

// ---------------------------------------------------------------------------
// merged weight split: one kernel handles up to 8 jobs.
// ---------------------------------------------------------------------------
struct SplitJob {
    const float* src;
    __nv_bfloat16 *hi, *lo;
    long n4;
    int C, ldd, col0;
};
struct SplitJobs {
    SplitJob j[8];
    long pre[9];
};

__global__ void split_all_kernel(SplitJobs jobs) {
    long i = (long)blockIdx.x * blockDim.x + threadIdx.x;
    if (i >= jobs.pre[8]) return;
    int k = 0;
    #pragma unroll
    for (int t = 0; t < 8; t++) if (i >= jobs.pre[t + 1]) k = t + 1;
    const SplitJob& J = jobs.j[k];
    long li = i - jobs.pre[k];
    float4 v = ((const float4*)J.src)[li];
    long e = li * 4;
    long r = e / J.C, c = e % J.C;
    long o = r * (long)J.ldd + J.col0 + c;
    __nv_bfloat16 h0 = __float2bfloat16(v.x), h1 = __float2bfloat16(v.y);
    __nv_bfloat16 h2 = __float2bfloat16(v.z), h3 = __float2bfloat16(v.w);
    *(__nv_bfloat162*)&J.hi[o]     = __nv_bfloat162(h0, h1);
    *(__nv_bfloat162*)&J.hi[o + 2] = __nv_bfloat162(h2, h3);
    *(__nv_bfloat162*)&J.lo[o]     = __nv_bfloat162(__float2bfloat16(v.x - __bfloat162float(h0)),
                                                    __float2bfloat16(v.y - __bfloat162float(h1)));
    *(__nv_bfloat162*)&J.lo[o + 2] = __nv_bfloat162(__float2bfloat16(v.z - __bfloat162float(h2)),
                                                    __float2bfloat16(v.w - __bfloat162float(h3)));
}

// ---------------------------------------------------------------------------
// block reductions
// ---------------------------------------------------------------------------
__device__ __forceinline__ float blockReduceSum(float v) {
    __shared__ float red[32];
    int lane = threadIdx.x & 31, w = threadIdx.x >> 5;
    #pragma unroll
    for (int o = 16; o; o >>= 1) v += __shfl_xor_sync(0xffffffffu, v, o);
    if (lane == 0) red[w] = v;
    __syncthreads();
    if (w == 0) {
        float x = (lane < (int)(blockDim.x >> 5)) ? red[lane] : 0.f;
        #pragma unroll
        for (int o = 16; o; o >>= 1) x += __shfl_xor_sync(0xffffffffu, x, o);
        if (lane == 0) red[0] = x;
    }
    __syncthreads();
    float r = red[0];
    __syncthreads();
    return r;
}
__device__ __forceinline__ float blockReduceMax(float v) {
    __shared__ float red[32];
    int lane = threadIdx.x & 31, w = threadIdx.x >> 5;
    #pragma unroll
    for (int o = 16; o; o >>= 1) v = fmaxf(v, __shfl_xor_sync(0xffffffffu, v, o));
    if (lane == 0) red[w] = v;
    __syncthreads();
    if (w == 0) {
        float x = (lane < (int)(blockDim.x >> 5)) ? red[lane] : -3.4e38f;
        #pragma unroll
        for (int o = 16; o; o >>= 1) x = fmaxf(x, __shfl_xor_sync(0xffffffffu, x, o));
        if (lane == 0) red[0] = x;
    }
    __syncthreads();
    float r = red[0];
    __syncthreads();
    return r;
}

// ---------------------------------------------------------------------------
// rmsnorm with strided input and fused hi/lo split output
// ---------------------------------------------------------------------------
__global__ void rmsnorm_split_kernel(const float* __restrict__ x, int ldx,
                                     const float* __restrict__ w,
                                     __nv_bfloat16* __restrict__ hi,
                                     __nv_bfloat16* __restrict__ lo, int N) {
    long row = blockIdx.x;
    const float* xr = x + row * ldx;
    float ss = 0.f;
    for (int i = threadIdx.x; i < N; i += blockDim.x) { float v = xr[i]; ss += v * v; }
    ss = blockReduceSum(ss);
    float inv = rsqrtf(ss / (float)N + EPS_);
    for (int i = threadIdx.x; i < N; i += blockDim.x) {
        float v = xr[i] * inv * w[i];
        __nv_bfloat16 h = __float2bfloat16(v);
        hi[row * N + i] = h;
        lo[row * N + i] = __float2bfloat16(v - __bfloat162float(h));
    }
}

// ---------------------------------------------------------------------------
// fused qas-rmsnorm + kprep (reads qkv). grid 2*S.
// ---------------------------------------------------------------------------
__global__ void qas_kprep_kernel(const float* __restrict__ qkv,
                                 const float* __restrict__ qw,
                                 const float* __restrict__ kw,
                                 const float* __restrict__ cosT,
                                 const float* __restrict__ sinT,
                                 __nv_bfloat16* __restrict__ qash,
                                 __nv_bfloat16* __restrict__ qasl,
                                 __nv_bfloat16* __restrict__ kfh,
                                 __nv_bfloat16* __restrict__ kfl) {
    long b = blockIdx.x;
    if (b < S_) {
        long row = b;
        const float* xr = qkv + row * NQKV_;
        float ss = 0.f;
        for (int i = threadIdx.x; i < QL_; i += blockDim.x) { float v = xr[i]; ss += v * v; }
        ss = blockReduceSum(ss);
        float inv = rsqrtf(ss / (float)QL_ + EPS_);
        for (int i = threadIdx.x; i < QL_; i += blockDim.x) {
            float v = xr[i] * inv * qw[i];
            __nv_bfloat16 h = __float2bfloat16(v);
            qash[row * QL_ + i] = h;
            qasl[row * QL_ + i] = __float2bfloat16(v - __bfloat162float(h));
        }
    } else {
        long s = b - S_;
        const float* row = qkv + s * NQKV_ + QL_;
        float ss = 0.f;
        for (int i = threadIdx.x; i < KVL_; i += blockDim.x) { float v = row[i]; ss += v * v; }
        ss = blockReduceSum(ss);
        float inv = rsqrtf(ss / (float)KVL_ + EPS_);
        for (int i = threadIdx.x; i < KVL_; i += blockDim.x) {
            float v = row[i] * inv * kw[i];
            __nv_bfloat16 h = __float2bfloat16(v);
            kfh[s * CF_ + i] = h;
            kfl[s * CF_ + i] = __float2bfloat16(v - __bfloat162float(h));
        }
        int i = threadIdx.x;
        if (i < DR_) {
            float x = row[KVL_ + i];
            float rot = (i < DR_ / 2) ? -row[KVL_ + i + DR_ / 2] : row[KVL_ + i - DR_ / 2];
            float v = x * cosT[s * DR_ + i] + rot * sinT[s * DR_ + i];
            __nv_bfloat16 h = __float2bfloat16(v);
            kfh[s * CF_ + KVL_ + i] = h;
            kfl[s * CF_ + KVL_ + i] = __float2bfloat16(v - __bfloat162float(h));
        }
    }
}

// ---------------------------------------------------------------------------
// q_pe rope. grid (S, H), 64 thr
// ---------------------------------------------------------------------------
__global__ void qrope_kernel(const __nv_bfloat16* __restrict__ qh,
                             const __nv_bfloat16* __restrict__ ql,
                             const float* __restrict__ cosT,
                             const float* __restrict__ sinT,
                             __nv_bfloat16* __restrict__ qfh,
                             __nv_bfloat16* __restrict__ qfl) {
    long s = blockIdx.x;
    int h = blockIdx.y;
    int i = threadIdx.x;
    long base = s * (long)(H_ * DF_) + h * DF_ + DN_;
    float x = __bfloat162float(qh[base + i]) + __bfloat162float(ql[base + i]);
    int j = (i < DR_ / 2) ? (i + DR_ / 2) : (i - DR_ / 2);
    float xr = __bfloat162float(qh[base + j]) + __bfloat162float(ql[base + j]);
    float rot = (i < DR_ / 2) ? -xr : xr;
    float v = x * cosT[s * DR_ + i] + rot * sinT[s * DR_ + i];
    long o = ((long)h * S_ + s) * CF_ + KVL_ + i;
    __nv_bfloat16 hh = __float2bfloat16(v);
    qfh[o] = hh;
    qfl[o] = __float2bfloat16(v - __bfloat162float(hh));
}

// ---------------------------------------------------------------------------
// causal softmax: scores fp32 -> attn hi/lo bf16; zero-fill to tile boundary.
// ---------------------------------------------------------------------------
__global__ void softmax_causal_kernel(const float* __restrict__ scores,
                                      __nv_bfloat16* __restrict__ ah,
                                      __nv_bfloat16* __restrict__ al) {
    long s = blockIdx.x;
    int h = blockIdx.y;
    const float* row = scores + ((long)h * S_ + s) * S_;
    __nv_bfloat16* hrow = ah + ((long)h * S_ + s) * S_;
    __nv_bfloat16* lrow = al + ((long)h * S_ + s) * S_;
    int L = (int)s + 1;
    int Lpad = (((int)s >> 7) + 1) << 7;
    float v[8];
    int cnt = 0;
    float m = -3.4e38f;
    for (int i = threadIdx.x; i < L; i += 256) { v[cnt] = row[i]; m = fmaxf(m, v[cnt]); cnt++; }
    m = blockReduceMax(m);
    float sum = 0.f;
    for (int j = 0; j < cnt; j++) { v[j] = __expf(v[j] - m); sum += v[j]; }
    sum = blockReduceSum(sum);
    float inv = 1.f / sum;
    cnt = 0;
    for (int i = threadIdx.x; i < L; i += 256) {
        float p = v[cnt++] * inv;
        __nv_bfloat16 hh = __float2bfloat16(p);
        hrow[i] = hh;
        lrow[i] = __float2bfloat16(p - __bfloat162float(hh));
    }
    __nv_bfloat16 z = __float2bfloat16(0.f);
    for (int i = L + threadIdx.x; i < Lpad; i += 256) { hrow[i] = z; lrow[i] = z; }
}

// ---------------------------------------------------------------------------
// swiglu: gu fp32 -> act hi/lo (float4 vectorized)
// ---------------------------------------------------------------------------
__global__ void swiglu_kernel(const float* __restrict__ gu,
                              __nv_bfloat16* __restrict__ ah,
                              __nv_bfloat16* __restrict__ al) {
    long i4 = (long)blockIdx.x * blockDim.x + threadIdx.x;
    if (i4 >= (long)S_ * I_ / 4) return;
    long s = i4 / (I_ / 4), c4 = i4 % (I_ / 4);
    float4 g = *(const float4*)&gu[s * (2L * I_) + c4 * 4];
    float4 u = *(const float4*)&gu[s * (2L * I_) + I_ + c4 * 4];
    float v0 = (g.x / (1.f + __expf(-g.x))) * u.x;
    float v1 = (g.y / (1.f + __expf(-g.y))) * u.y;
    float v2 = (g.z / (1.f + __expf(-g.z))) * u.z;
    float v3 = (g.w / (1.f + __expf(-g.w))) * u.w;
    __nv_bfloat16 h0 = __float2bfloat16(v0), h1 = __float2bfloat16(v1);
    __nv_bfloat16 h2 = __float2bfloat16(v2), h3 = __float2bfloat16(v3);
    long o = s * (long)I_ + c4 * 4;
    *(__nv_bfloat162*)&ah[o]     = __nv_bfloat162(h0, h1);
    *(__nv_bfloat162*)&ah[o + 2] = __nv_bfloat162(h2, h3);
    *(__nv_bfloat162*)&al[o]     = __nv_bfloat162(__float2bfloat16(v0 - __bfloat162float(h0)),
                                                  __float2bfloat16(v1 - __bfloat162float(h1)));
    *(__nv_bfloat162*)&al[o + 2] = __nv_bfloat162(__float2bfloat16(v2 - __bfloat162float(h2)),
                                                  __float2bfloat16(v3 - __bfloat162float(h3)));
}

// ---------------------------------------------------------------------------
// host orchestration
// ---------------------------------------------------------------------------
#define SMEM_T  (2 * (2 * TILE_A + 2 * TILE_BT))   // 75776
#define SMEM_NT (2 * (2 * TILE_A + 2 * TILE_BN))   // 81920

struct GArgs {
    const __nv_bfloat16 *Ah, *Al, *Bh, *Bl;
    int lda, ldb, ldc, M, N, K, batch, causal, ldad;
    long sA, sB, sC, sAd;
    float *Cf, alpha;
    __nv_bfloat16 *Chi, *Clo;
    const float* add;
};

static void launch_g(bool btrans, const GArgs& a, cudaStream_t st) {
    dim3 grid(a.M / 128, (a.N + 127) / 128, a.batch);
    if (btrans)
        gemm_tc<1><<<grid, 128, SMEM_T, st>>>(a.Ah, a.Al, a.lda, a.sA, a.Bh, a.Bl, a.ldb, a.sB,
                                              a.Cf, a.Chi, a.Clo, a.ldc, a.sC,
                                              a.M, a.N, a.K, a.alpha, a.add, a.ldad, a.sAd, a.causal);
    else
        gemm_tc<0><<<grid, 128, SMEM_NT, st>>>(a.Ah, a.Al, a.lda, a.sA, a.Bh, a.Bl, a.ldb, a.sB,
                                               a.Cf, a.Chi, a.Clo, a.ldc, a.sC,
                                               a.M, a.N, a.K, a.alpha, a.add, a.ldad, a.sAd, a.causal);
}

extern "C" void kernel_launch(void* const* d_in, const int* in_sizes, int n_in,
                              void* d_out, int out_size) {
    const float* hidden    = (const float*)d_in[0];
    const float* cosT      = (const float*)d_in[1];
    const float* sinT      = (const float*)d_in[2];
    const float* ln1_w     = (const float*)d_in[3];
    const float* q_a_w     = (const float*)d_in[4];
    const float* q_a_ln_w  = (const float*)d_in[5];
    const float* q_b_w     = (const float*)d_in[6];
    const float* kv_a_w    = (const float*)d_in[7];
    const float* kv_a_ln_w = (const float*)d_in[8];
    const float* kc_w      = (const float*)d_in[9];
    const float* vc_w      = (const float*)d_in[10];
    const float* o_w       = (const float*)d_in[11];
    const float* ln2_w     = (const float*)d_in[12];
    const float* gate_up_w = (const float*)d_in[13];
    const float* down_w    = (const float*)d_in[14];
    float* out             = (float*)d_out;

    cudaFuncSetAttribute(gemm_tc<1>, cudaFuncAttributeMaxDynamicSharedMemorySize, SMEM_T);
    cudaFuncSetAttribute(gemm_tc<0>, cudaFuncAttributeMaxDynamicSharedMemorySize, SMEM_NT);

    float* sc = nullptr;
    cudaGetSymbolAddress((void**)&sc, g_scratch);
    __nv_bfloat16* bf = nullptr;
    cudaGetSymbolAddress((void**)&bf, g_bf);

    float* qkv    = sc + OFF_QKV;
    float* scores = sc + OFF_SCORES;
    float* hid2   = sc + OFF_HID2;
    float* gu     = sc + OFF_GU;

    auto HI = [&](long off) { return bf + off; };
    auto LO = [&](long off, long E) { return bf + off + E; };

    // side stream + events
    cudaStream_t s2;
    cudaStreamCreate(&s2);
    cudaEvent_t e0, e_w, e_att, e_s0;
    cudaEventCreateWithFlags(&e0,    cudaEventDisableTiming);
    cudaEventCreateWithFlags(&e_w,   cudaEventDisableTiming);
    cudaEventCreateWithFlags(&e_att, cudaEventDisableTiming);
    cudaEventCreateWithFlags(&e_s0,  cudaEventDisableTiming);

    // --- critical weight split (WQKV only) on main ---
    {
        SplitJobs js{};
        js.j[0] = {q_a_w,  HI(B_WQKV), LO(B_WQKV, E_WQKV), ((long)D_ * QL_) / 4, QL_, NQKV_, 0};
        js.j[1] = {kv_a_w, HI(B_WQKV), LO(B_WQKV, E_WQKV), ((long)D_ * CF_) / 4, CF_, NQKV_, QL_};
        js.pre[0] = 0;
        for (int k = 0; k < 8; k++) js.pre[k + 1] = js.pre[k] + js.j[k].n4;
        split_all_kernel<<<(unsigned)((js.pre[8] + 255) / 256), 256>>>(js);
    }

    // fork: remaining weight splits on s2
    cudaEventRecord(e0, 0);
    cudaStreamWaitEvent(s2, e0, 0);
    {
        SplitJobs js{};
        js.j[0] = {q_b_w,     HI(B_WQB), LO(B_WQB, E_WQB), E_WQB / 4, H_ * DF_, H_ * DF_, 0};
        js.j[1] = {kc_w,      HI(B_WKC), LO(B_WKC, E_WKC), E_WKC / 4, KVL_, KVL_, 0};
        js.j[2] = {vc_w,      HI(B_WVC), LO(B_WVC, E_WVC), E_WVC / 4, DV_, DV_, 0};
        js.j[3] = {o_w,       HI(B_WO),  LO(B_WO,  E_WO),  E_WO / 4,  D_, D_, 0};
        js.j[4] = {gate_up_w, HI(B_WGU), LO(B_WGU, E_WGU), E_WGU / 4, 2 * I_, 2 * I_, 0};
        js.j[5] = {down_w,    HI(B_WDN), LO(B_WDN, E_WDN), E_WDN / 4, D_, D_, 0};
        js.pre[0] = 0;
        for (int k = 0; k < 8; k++) js.pre[k + 1] = js.pre[k] + js.j[k].n4;
        split_all_kernel<<<(unsigned)((js.pre[8] + 255) / 256), 256, 0, s2>>>(js);
    }
    cudaEventRecord(e_w, s2);

    // 1. h = rmsnorm(hidden) -> hi/lo
    rmsnorm_split_kernel<<<S_, 256>>>(hidden, D_, ln1_w, HI(B_HS), LO(B_HS, E_HS), D_);

    GArgs a{};

    // 2. qkv = h @ [q_a_w | kv_a_w]   (fused, fp32 out, N=2112)
    a = {HI(B_HS), LO(B_HS, E_HS), HI(B_WQKV), LO(B_WQKV, E_WQKV),
         D_, NQKV_, NQKV_, S_, NQKV_, D_, 1, 0, 0, 0, 0, 0, 0,
         qkv, 1.f, nullptr, nullptr, nullptr};
    launch_g(true, a, 0);

    // 3+5. fused: qas = rmsnorm(qkv[:, :1536]); kf = [rmsnorm, rope] -> hi/lo
    qas_kprep_kernel<<<2 * S_, 256>>>(qkv, q_a_ln_w, kv_a_ln_w, cosT, sinT,
                                      HI(B_QAS), LO(B_QAS, E_QAS),
                                      HI(B_KFS), LO(B_KFS, E_KFS));

    // join: all weights split before the q GEMM
    cudaStreamWaitEvent(0, e_w, 0);

    // 4. q = qas @ q_b_w -> hi/lo
    a = {HI(B_QAS), LO(B_QAS, E_QAS), HI(B_WQB), LO(B_WQB, E_WQB),
         QL_, H_ * DF_, H_ * DF_, S_, H_ * DF_, QL_, 1, 0, 0, 0, 0, 0, 0,
         nullptr, 1.f, HI(B_QS), LO(B_QS, E_QS), nullptr};
    launch_g(true, a, 0);

    // 6. qf[:, :512] = q_nope @ kc_w per head -> hi/lo
    a = {HI(B_QS), LO(B_QS, E_QS), HI(B_WKC), LO(B_WKC, E_WKC),
         H_ * DF_, KVL_, CF_, S_, KVL_, DN_, H_, 0, 0,
         (long)DF_, (long)DN_ * KVL_, (long)S_ * CF_, 0,
         nullptr, 1.f, HI(B_QFS), LO(B_QFS, E_QFS), nullptr};
    launch_g(true, a, 0);

    // 7. qf[:, 512:576] = rope(q_pe) -> hi/lo
    qrope_kernel<<<dim3(S_, H_), DR_>>>(HI(B_QS), LO(B_QS, E_QS), cosT, sinT,
                                        HI(B_QFS), LO(B_QFS, E_QFS));

    // ---- attention pipelined in two head-groups (8 heads each) ----
    const int HG = H_ / 2;

    // 8a. scores group0 on main
    a = {HI(B_QFS), LO(B_QFS, E_QFS), HI(B_KFS), LO(B_KFS, E_KFS),
         CF_, CF_, S_, S_, S_, CF_, HG, 1, 0,
         (long)S_ * CF_, 0, (long)S_ * S_, 0,
         scores, SCALE_, nullptr, nullptr, nullptr};
    launch_g(false, a, 0);
    cudaEventRecord(e_s0, 0);

    // 8b. scores group1 on main
    a.Ah = HI(B_QFS) + (long)HG * S_ * CF_;
    a.Al = LO(B_QFS, E_QFS) + (long)HG * S_ * CF_;
    a.Cf = scores + (long)HG * S_ * S_;
    launch_g(false, a, 0);

    // 9a+10a. softmax+olat group0 on s2 (overlaps scores group1)
    cudaStreamWaitEvent(s2, e_s0, 0);
    softmax_causal_kernel<<<dim3(S_, HG), 256, 0, s2>>>(
        scores, HI(B_ATT), LO(B_ATT, E_ATT));
    a = {HI(B_ATT), LO(B_ATT, E_ATT), HI(B_KFS), LO(B_KFS, E_KFS),
         S_, CF_, KVL_, S_, KVL_, S_, HG, 2, 0,
         (long)S_ * S_, 0, (long)S_ * KVL_, 0,
         nullptr, 1.f, HI(B_OLS), LO(B_OLS, E_OLS), nullptr};
    launch_g(true, a, s2);
    cudaEventRecord(e_att, s2);

    // 9b+10b. softmax+olat group1 on main
    softmax_causal_kernel<<<dim3(S_, HG), 256>>>(
        scores + (long)HG * S_ * S_,
        HI(B_ATT) + (long)HG * S_ * S_,
        LO(B_ATT, E_ATT) + (long)HG * S_ * S_);
    a = {HI(B_ATT) + (long)HG * S_ * S_, LO(B_ATT, E_ATT) + (long)HG * S_ * S_,
         HI(B_KFS), LO(B_KFS, E_KFS),
         S_, CF_, KVL_, S_, KVL_, S_, HG, 2, 0,
         (long)S_ * S_, 0, (long)S_ * KVL_, 0,
         nullptr, 1.f, HI(B_OLS) + (long)HG * S_ * KVL_,
         LO(B_OLS, E_OLS) + (long)HG * S_ * KVL_, nullptr};
    launch_g(true, a, 0);

    // join: all olat done before vc GEMM
    cudaStreamWaitEvent(0, e_att, 0);

    // 11. o[:, h*128:] = olat @ vc_w per head -> hi/lo
    a = {HI(B_OLS), LO(B_OLS, E_OLS), HI(B_WVC), LO(B_WVC, E_WVC),
         KVL_, DV_, H_ * DV_, S_, DV_, KVL_, H_, 0, 0,
         (long)S_ * KVL_, (long)KVL_ * DV_, (long)DV_, 0,
         nullptr, 1.f, HI(B_OS), LO(B_OS, E_OS), nullptr};
    launch_g(true, a, 0);

    // 12. hid2 = o @ o_w + hidden  (fp32)
    a = {HI(B_OS), LO(B_OS, E_OS), HI(B_WO), LO(B_WO, E_WO),
         H_ * DV_, D_, D_, S_, D_, H_ * DV_, 1, 0, D_, 0, 0, 0, 0,
         hid2, 1.f, nullptr, nullptr, hidden};
    launch_g(true, a, 0);

    // 13. x2 = rmsnorm(hid2) -> hi/lo
    rmsnorm_split_kernel<<<S_, 256>>>(hid2, D_, ln2_w, HI(B_X2S), LO(B_X2S, E_X2S), D_);

    // 14. gu = x2 @ gate_up_w  (fp32)
    a = {HI(B_X2S), LO(B_X2S, E_X2S), HI(B_WGU), LO(B_WGU, E_WGU),
         D_, 2 * I_, 2 * I_, S_, 2 * I_, D_, 1, 0, 0, 0, 0, 0, 0,
         gu, 1.f, nullptr, nullptr, nullptr};
    launch_g(true, a, 0);

    // 15. act = swiglu(gu) -> hi/lo  (float4)
    {
        long total4 = (long)S_ * I_ / 4;
        swiglu_kernel<<<(unsigned)((total4 + 255) / 256), 256>>>(gu, HI(B_ACTS), LO(B_ACTS, E_ACTS));
    }

    // 16. out = act @ down_w + hid2  (fp32)
    a = {HI(B_ACTS), LO(B_ACTS, E_ACTS), HI(B_WDN), LO(B_WDN, E_WDN),
         I_, D_, D_, S_, D_, I_, 1, 0, D_, 0, 0, 0, 0,
         out, 1.f, nullptr, nullptr, hid2};
    launch_g(true, a, 0);
}